// round 1
// baseline (speedup 1.0000x reference)
#include <cuda_runtime.h>
#include <cuda_bf16.h>

// Damping_27066883900008: per-row fused dual-MLP + damping matrix epilogue.
// B = 4,194,304 rows. One thread per row, weights staged in shared memory.

#define NTHREADS 256

// Accurate tanh via tanh(x) = 1 - 2/(exp(2x)+1).
// __expf -> MUFU.EX2 (+FMUL), __fdividef -> MUFU.RCP (+FMUL). ~1e-6 abs error.
// Clamp positive side so exp never overflows (2*44 = 88 < ln(FLT_MAX)).
__device__ __forceinline__ float tanh_fast(float x) {
    float xc = fminf(x, 44.0f);
    float e  = __expf(xc + xc);
    return 1.0f - __fdividef(2.0f, e + 1.0f);
}

__global__ __launch_bounds__(NTHREADS) void damping_kernel(
    const float2* __restrict__ x,
    const float*  __restrict__ w_d1, const float* __restrict__ w_d2,
    const float*  __restrict__ w_d3, const float* __restrict__ w_o1,
    const float*  __restrict__ w_o2, const float* __restrict__ w_o3,
    const float*  __restrict__ b_d1, const float* __restrict__ b_d2,
    const float*  __restrict__ b_d3, const float* __restrict__ b_o1,
    const float*  __restrict__ b_o2, const float* __restrict__ b_o3,
    float2* __restrict__ out, int nrows)
{
    // Shared-staged parameters (broadcast reads -> conflict-free LDS).
    __shared__ __align__(16) float s_wd1[32];   // (2,16) row-major
    __shared__ __align__(16) float s_wd2[256];  // (16,16)
    __shared__ __align__(16) float s_wd3[32];   // (16,2)
    __shared__ __align__(16) float s_wo1[32];
    __shared__ __align__(16) float s_wo2[256];
    __shared__ __align__(16) float s_wo3[16];   // (16,1)
    __shared__ __align__(16) float s_bd1[16], s_bd2[16], s_bd3[2];
    __shared__ __align__(16) float s_bo1[16], s_bo2[16], s_bo3[1];

    const int t = threadIdx.x;
    if (t < 256) { s_wd2[t] = w_d2[t]; s_wo2[t] = w_o2[t]; }
    if (t < 32)  { s_wd1[t] = w_d1[t]; s_wd3[t] = w_d3[t]; s_wo1[t] = w_o1[t]; }
    if (t < 16)  { s_wo3[t] = w_o3[t]; s_bd1[t] = b_d1[t]; s_bd2[t] = b_d2[t];
                   s_bo1[t] = b_o1[t]; s_bo2[t] = b_o2[t]; }
    if (t < 2)   { s_bd3[t] = b_d3[t]; }
    if (t == 0)  { s_bo3[0] = b_o3[0]; }
    __syncthreads();

    const int r = blockIdx.x * NTHREADS + t;
    if (r >= nrows) return;

    const float2 xi = x[r];
    const float x0 = xi.x, x1 = xi.y;

    float h[16];   // layer-1 activations
    float acc[16]; // layer-2 accumulators

    // ---------------- d-net ----------------
    #pragma unroll
    for (int j = 0; j < 16; j++)
        h[j] = tanh_fast(fmaf(x0, s_wd1[j], fmaf(x1, s_wd1[16 + j], s_bd1[j])));

    #pragma unroll
    for (int j = 0; j < 16; j++) acc[j] = s_bd2[j];
    #pragma unroll
    for (int k = 0; k < 16; k++) {
        const float hk = h[k];
        #pragma unroll
        for (int j4 = 0; j4 < 4; j4++) {
            const float4 w = *reinterpret_cast<const float4*>(&s_wd2[k * 16 + j4 * 4]);
            acc[j4 * 4 + 0] = fmaf(hk, w.x, acc[j4 * 4 + 0]);
            acc[j4 * 4 + 1] = fmaf(hk, w.y, acc[j4 * 4 + 1]);
            acc[j4 * 4 + 2] = fmaf(hk, w.z, acc[j4 * 4 + 2]);
            acc[j4 * 4 + 3] = fmaf(hk, w.w, acc[j4 * 4 + 3]);
        }
    }

    float d30 = s_bd3[0], d31 = s_bd3[1];
    #pragma unroll
    for (int k = 0; k < 16; k++) {
        const float g = tanh_fast(acc[k]);
        d30 = fmaf(g, s_wd3[k * 2 + 0], d30);
        d31 = fmaf(g, s_wd3[k * 2 + 1], d31);
    }
    const float a = (fmaxf(d30, 0.0f) + 0.001f) * x0;
    const float b = (fmaxf(d31, 0.0f) + 0.001f) * x1;

    // ---------------- o-net ----------------
    #pragma unroll
    for (int j = 0; j < 16; j++)
        h[j] = tanh_fast(fmaf(x0, s_wo1[j], fmaf(x1, s_wo1[16 + j], s_bo1[j])));

    #pragma unroll
    for (int j = 0; j < 16; j++) acc[j] = s_bo2[j];
    #pragma unroll
    for (int k = 0; k < 16; k++) {
        const float hk = h[k];
        #pragma unroll
        for (int j4 = 0; j4 < 4; j4++) {
            const float4 w = *reinterpret_cast<const float4*>(&s_wo2[k * 16 + j4 * 4]);
            acc[j4 * 4 + 0] = fmaf(hk, w.x, acc[j4 * 4 + 0]);
            acc[j4 * 4 + 1] = fmaf(hk, w.y, acc[j4 * 4 + 1]);
            acc[j4 * 4 + 2] = fmaf(hk, w.z, acc[j4 * 4 + 2]);
            acc[j4 * 4 + 3] = fmaf(hk, w.w, acc[j4 * 4 + 3]);
        }
    }

    float c = s_bo3[0];
    #pragma unroll
    for (int k = 0; k < 16; k++)
        c = fmaf(tanh_fast(acc[k]), s_wo3[k], c);

    // ---------------- damping-matrix epilogue ----------------
    const float ac = a * c;
    const float D0 = fmaf(a * a, x0, ac * x1);
    const float D1 = fmaf(ac, x0, fmaf(c, c, b * b) * x1);

    out[r] = make_float2(D0, D1);
}

extern "C" void kernel_launch(void* const* d_in, const int* in_sizes, int n_in,
                              void* d_out, int out_size) {
    const float2* x   = (const float2*)d_in[0];
    const float* w_d1 = (const float*)d_in[1];
    const float* w_d2 = (const float*)d_in[2];
    const float* w_d3 = (const float*)d_in[3];
    const float* w_o1 = (const float*)d_in[4];
    const float* w_o2 = (const float*)d_in[5];
    const float* w_o3 = (const float*)d_in[6];
    const float* b_d1 = (const float*)d_in[7];
    const float* b_d2 = (const float*)d_in[8];
    const float* b_d3 = (const float*)d_in[9];
    const float* b_o1 = (const float*)d_in[10];
    const float* b_o2 = (const float*)d_in[11];
    const float* b_o3 = (const float*)d_in[12];
    float2* out = (float2*)d_out;

    const int nrows = in_sizes[0] / 2;
    const int grid  = (nrows + NTHREADS - 1) / NTHREADS;

    damping_kernel<<<grid, NTHREADS>>>(x, w_d1, w_d2, w_d3, w_o1, w_o2, w_o3,
                                       b_d1, b_d2, b_d3, b_o1, b_o2, b_o3,
                                       out, nrows);
}

// round 2
// speedup vs baseline: 1.2620x; 1.2620x over previous
#include <cuda_runtime.h>
#include <cuda_bf16.h>

// Damping_27066883900008 R2: net-packed f32x2 (d-net in lo lane, o-net in hi
// lane) + MUFU.TANH. One row per thread.

#define NTHREADS 256
typedef unsigned long long ull;

__device__ __forceinline__ ull pack2(float lo, float hi) {
    ull r; asm("mov.b64 %0, {%1, %2};" : "=l"(r) : "f"(lo), "f"(hi)); return r;
}
__device__ __forceinline__ void unpack2(ull v, float& lo, float& hi) {
    asm("mov.b64 {%0, %1}, %2;" : "=f"(lo), "=f"(hi) : "l"(v));
}
__device__ __forceinline__ ull fma2(ull a, ull b, ull c) {
    ull d; asm("fma.rn.f32x2 %0, %1, %2, %3;" : "=l"(d) : "l"(a), "l"(b), "l"(c)); return d;
}
__device__ __forceinline__ float tanh_ap(float x) {
    float y; asm("tanh.approx.f32 %0, %1;" : "=f"(y) : "f"(x)); return y;
}
__device__ __forceinline__ ull tanh2(ull v) {
    float lo, hi; unpack2(v, lo, hi);
    return pack2(tanh_ap(lo), tanh_ap(hi));
}

struct U2 { ull x, y; };

__global__ __launch_bounds__(NTHREADS) void damping_kernel(
    const float2* __restrict__ x,
    const float*  __restrict__ w_d1, const float* __restrict__ w_d2,
    const float*  __restrict__ w_d3, const float* __restrict__ w_o1,
    const float*  __restrict__ w_o2, const float* __restrict__ w_o3,
    const float*  __restrict__ b_d1, const float* __restrict__ b_d2,
    const float*  __restrict__ b_d3, const float* __restrict__ b_o1,
    const float*  __restrict__ b_o2, const float* __restrict__ b_o3,
    float2* __restrict__ out, int nrows)
{
    // Packed weights: lo lane = d-net, hi lane = o-net.
    __shared__ __align__(16) ull s_w1p[32];    // (2,16) j-major, packed {wd1,wo1}
    __shared__ __align__(16) ull s_w2p[256];   // (16,16) packed {wd2,wo2}
    __shared__ __align__(16) ull s_b1p[16];    // {bd1,bo1}
    __shared__ __align__(16) ull s_b2p[16];    // {bd2,bo2}
    __shared__ __align__(16) float s_wd3[32];  // (16,2) scalar
    __shared__ __align__(16) float s_wo3[16];  // (16,1) scalar
    __shared__ float s_bd3[2], s_bo3[1];

    const int t = threadIdx.x;
    if (t < 256) s_w2p[t] = pack2(w_d2[t], w_o2[t]);
    if (t < 32)  { s_w1p[t] = pack2(w_d1[t], w_o1[t]); s_wd3[t] = w_d3[t]; }
    if (t < 16)  { s_b1p[t] = pack2(b_d1[t], b_o1[t]);
                   s_b2p[t] = pack2(b_d2[t], b_o2[t]);
                   s_wo3[t] = w_o3[t]; }
    if (t < 2)   s_bd3[t] = b_d3[t];
    if (t == 0)  s_bo3[0] = b_o3[0];
    __syncthreads();

    const int r = blockIdx.x * NTHREADS + t;
    if (r >= nrows) return;

    const float2 xi = x[r];
    const ull x0p = pack2(xi.x, xi.x);
    const ull x1p = pack2(xi.y, xi.y);

    // ---------------- layer 1 (both nets packed) ----------------
    ull h[16];
    #pragma unroll
    for (int j = 0; j < 16; j++)
        h[j] = tanh2(fma2(x0p, s_w1p[j], fma2(x1p, s_w1p[16 + j], s_b1p[j])));

    // ---------------- layer 2 (16x16, both nets packed) ----------------
    ull acc[16];
    #pragma unroll
    for (int j = 0; j < 16; j++) acc[j] = s_b2p[j];
    #pragma unroll
    for (int k = 0; k < 16; k++) {
        const ull hk = h[k];
        #pragma unroll
        for (int j2 = 0; j2 < 8; j2++) {
            // 128-bit shared load: two packed weight pairs, broadcast address
            const U2 w = *reinterpret_cast<const U2*>(&s_w2p[k * 16 + j2 * 2]);
            acc[j2 * 2 + 0] = fma2(hk, w.x, acc[j2 * 2 + 0]);
            acc[j2 * 2 + 1] = fma2(hk, w.y, acc[j2 * 2 + 1]);
        }
    }

    // ---------------- layer 3 (scalar, nets diverge) ----------------
    float d30 = s_bd3[0], d31 = s_bd3[1], c = s_bo3[0];
    #pragma unroll
    for (int k = 0; k < 16; k++) {
        float pd, po; unpack2(acc[k], pd, po);
        const float gd = tanh_ap(pd);
        const float go = tanh_ap(po);
        d30 = fmaf(gd, s_wd3[k * 2 + 0], d30);
        d31 = fmaf(gd, s_wd3[k * 2 + 1], d31);
        c   = fmaf(go, s_wo3[k], c);
    }

    const float a = (fmaxf(d30, 0.0f) + 0.001f) * xi.x;
    const float b = (fmaxf(d31, 0.0f) + 0.001f) * xi.y;

    // ---------------- damping-matrix epilogue ----------------
    const float ac = a * c;
    const float D0 = fmaf(a * a, xi.x, ac * xi.y);
    const float D1 = fmaf(ac, xi.x, fmaf(c, c, b * b) * xi.y);

    out[r] = make_float2(D0, D1);
}

extern "C" void kernel_launch(void* const* d_in, const int* in_sizes, int n_in,
                              void* d_out, int out_size) {
    const float2* x   = (const float2*)d_in[0];
    const float* w_d1 = (const float*)d_in[1];
    const float* w_d2 = (const float*)d_in[2];
    const float* w_d3 = (const float*)d_in[3];
    const float* w_o1 = (const float*)d_in[4];
    const float* w_o2 = (const float*)d_in[5];
    const float* w_o3 = (const float*)d_in[6];
    const float* b_d1 = (const float*)d_in[7];
    const float* b_d2 = (const float*)d_in[8];
    const float* b_d3 = (const float*)d_in[9];
    const float* b_o1 = (const float*)d_in[10];
    const float* b_o2 = (const float*)d_in[11];
    const float* b_o3 = (const float*)d_in[12];
    float2* out = (float2*)d_out;

    const int nrows = in_sizes[0] / 2;
    const int grid  = (nrows + NTHREADS - 1) / NTHREADS;

    damping_kernel<<<grid, NTHREADS>>>(x, w_d1, w_d2, w_d3, w_o1, w_o2, w_o3,
                                       b_d1, b_d2, b_d3, b_o1, b_o2, b_o3,
                                       out, nrows);
}

// round 4
// speedup vs baseline: 1.8575x; 1.4718x over previous
#include <cuda_runtime.h>
#include <cuda_bf16.h>

// Damping_27066883900008 R4 (= R3 resubmit; R3 hit a transient device-busy
// infra failure before any kernel ran).
// 2 rows/thread (halves shared-weight refetch), layer-1 fused into k-loop
// (no h[] array), net-packed f32x2, MUFU.TANH.

#define NTHREADS 256
typedef unsigned long long ull;

__device__ __forceinline__ ull pack2(float lo, float hi) {
    ull r; asm("mov.b64 %0, {%1, %2};" : "=l"(r) : "f"(lo), "f"(hi)); return r;
}
__device__ __forceinline__ void unpack2(ull v, float& lo, float& hi) {
    asm("mov.b64 {%0, %1}, %2;" : "=f"(lo), "=f"(hi) : "l"(v));
}
__device__ __forceinline__ ull fma2(ull a, ull b, ull c) {
    ull d; asm("fma.rn.f32x2 %0, %1, %2, %3;" : "=l"(d) : "l"(a), "l"(b), "l"(c)); return d;
}
__device__ __forceinline__ float tanh_ap(float x) {
    float y; asm("tanh.approx.f32 %0, %1;" : "=f"(y) : "f"(x)); return y;
}
__device__ __forceinline__ ull tanh2(ull v) {
    float lo, hi; unpack2(v, lo, hi);
    return pack2(tanh_ap(lo), tanh_ap(hi));
}

struct U2 { ull x, y; };

__global__ __launch_bounds__(NTHREADS, 2) void damping_kernel(
    const float4* __restrict__ x,
    const float*  __restrict__ w_d1, const float* __restrict__ w_d2,
    const float*  __restrict__ w_d3, const float* __restrict__ w_o1,
    const float*  __restrict__ w_o2, const float* __restrict__ w_o3,
    const float*  __restrict__ b_d1, const float* __restrict__ b_d2,
    const float*  __restrict__ b_d3, const float* __restrict__ b_o1,
    const float*  __restrict__ b_o2, const float* __restrict__ b_o3,
    float4* __restrict__ out, int npairs)
{
    // Packed weights: lo lane = d-net, hi lane = o-net.
    __shared__ __align__(16) ull s_w2p[256];   // (16,16) packed {wd2,wo2}
    __shared__ __align__(16) ull s_w1p[32];    // (2,16) packed {wd1,wo1}
    __shared__ __align__(16) ull s_b1p[16];    // {bd1,bo1}
    __shared__ __align__(16) ull s_b2p[16];    // {bd2,bo2}
    __shared__ __align__(16) float s_wd3[32];  // (16,2)
    __shared__ __align__(16) float s_wo3[16];  // (16,1)
    __shared__ float s_bd3[2], s_bo3[1];

    const int t = threadIdx.x;
    if (t < 256) s_w2p[t] = pack2(w_d2[t], w_o2[t]);
    if (t < 32)  { s_w1p[t] = pack2(w_d1[t], w_o1[t]); s_wd3[t] = w_d3[t]; }
    if (t < 16)  { s_b1p[t] = pack2(b_d1[t], b_o1[t]);
                   s_b2p[t] = pack2(b_d2[t], b_o2[t]);
                   s_wo3[t] = w_o3[t]; }
    if (t < 2)   s_bd3[t] = b_d3[t];
    if (t == 0)  s_bo3[0] = b_o3[0];
    __syncthreads();

    const int p = blockIdx.x * NTHREADS + t;
    if (p >= npairs) return;

    // Two adjacent rows per thread: A = 2p, B = 2p+1 -> one float4.
    const float4 xi = x[p];
    const ull x0A = pack2(xi.x, xi.x), x1A = pack2(xi.y, xi.y);
    const ull x0B = pack2(xi.z, xi.z), x1B = pack2(xi.w, xi.w);

    // ---------------- fused layer-1 + layer-2 ----------------
    ull accA[16], accB[16];
    #pragma unroll
    for (int j = 0; j < 16; j++) { accA[j] = s_b2p[j]; accB[j] = accA[j]; }

    #pragma unroll
    for (int k = 0; k < 16; k++) {
        // layer-1 activation for this k, both rows (packed d/o nets)
        const ull w1k0 = s_w1p[k];
        const ull w1k1 = s_w1p[16 + k];
        const ull b1k  = s_b1p[k];
        const ull hA = tanh2(fma2(x0A, w1k0, fma2(x1A, w1k1, b1k)));
        const ull hB = tanh2(fma2(x0B, w1k0, fma2(x1B, w1k1, b1k)));

        // layer-2 j-sweep: each weight load feeds BOTH rows
        #pragma unroll
        for (int j2 = 0; j2 < 8; j2++) {
            const U2 w = *reinterpret_cast<const U2*>(&s_w2p[k * 16 + j2 * 2]);
            accA[j2 * 2 + 0] = fma2(hA, w.x, accA[j2 * 2 + 0]);
            accA[j2 * 2 + 1] = fma2(hA, w.y, accA[j2 * 2 + 1]);
            accB[j2 * 2 + 0] = fma2(hB, w.x, accB[j2 * 2 + 0]);
            accB[j2 * 2 + 1] = fma2(hB, w.y, accB[j2 * 2 + 1]);
        }
    }

    // ---------------- layer 3 (scalar, nets diverge) ----------------
    float d30A = s_bd3[0], d31A = s_bd3[1], cA = s_bo3[0];
    float d30B = d30A,     d31B = d31A,     cB = cA;
    #pragma unroll
    for (int k = 0; k < 16; k++) {
        const float w3a = s_wd3[k * 2 + 0];
        const float w3b = s_wd3[k * 2 + 1];
        const float w3c = s_wo3[k];
        float pdA, poA; unpack2(accA[k], pdA, poA);
        float pdB, poB; unpack2(accB[k], pdB, poB);
        const float gdA = tanh_ap(pdA), goA = tanh_ap(poA);
        const float gdB = tanh_ap(pdB), goB = tanh_ap(poB);
        d30A = fmaf(gdA, w3a, d30A);  d30B = fmaf(gdB, w3a, d30B);
        d31A = fmaf(gdA, w3b, d31A);  d31B = fmaf(gdB, w3b, d31B);
        cA   = fmaf(goA, w3c, cA);    cB   = fmaf(goB, w3c, cB);
    }

    // ---------------- damping-matrix epilogue ----------------
    const float aA = (fmaxf(d30A, 0.0f) + 0.001f) * xi.x;
    const float bA = (fmaxf(d31A, 0.0f) + 0.001f) * xi.y;
    const float aB = (fmaxf(d30B, 0.0f) + 0.001f) * xi.z;
    const float bB = (fmaxf(d31B, 0.0f) + 0.001f) * xi.w;

    const float acA = aA * cA;
    const float acB = aB * cB;
    float4 o;
    o.x = fmaf(aA * aA, xi.x, acA * xi.y);
    o.y = fmaf(acA, xi.x, fmaf(cA, cA, bA * bA) * xi.y);
    o.z = fmaf(aB * aB, xi.z, acB * xi.w);
    o.w = fmaf(acB, xi.z, fmaf(cB, cB, bB * bB) * xi.w);
    out[p] = o;
}

extern "C" void kernel_launch(void* const* d_in, const int* in_sizes, int n_in,
                              void* d_out, int out_size) {
    const float4* x   = (const float4*)d_in[0];
    const float* w_d1 = (const float*)d_in[1];
    const float* w_d2 = (const float*)d_in[2];
    const float* w_d3 = (const float*)d_in[3];
    const float* w_o1 = (const float*)d_in[4];
    const float* w_o2 = (const float*)d_in[5];
    const float* w_o3 = (const float*)d_in[6];
    const float* b_d1 = (const float*)d_in[7];
    const float* b_d2 = (const float*)d_in[8];
    const float* b_d3 = (const float*)d_in[9];
    const float* b_o1 = (const float*)d_in[10];
    const float* b_o2 = (const float*)d_in[11];
    const float* b_o3 = (const float*)d_in[12];
    float4* out = (float4*)d_out;

    const int nrows  = in_sizes[0] / 2;
    const int npairs = nrows / 2;               // B = 4194304 is even
    const int grid   = (npairs + NTHREADS - 1) / NTHREADS;

    damping_kernel<<<grid, NTHREADS>>>(x, w_d1, w_d2, w_d3, w_o1, w_o2, w_o3,
                                       b_d1, b_d2, b_d3, b_o1, b_o2, b_o3,
                                       out, npairs);
}

// round 5
// speedup vs baseline: 2.2013x; 1.1851x over previous
#include <cuda_runtime.h>
#include <cuda_bf16.h>

// Damping_27066883900008 R5: weights moved from shared memory to __constant__
// (uniform-port LDCU path, off L1TEX). Prep kernel packs {d,o} pairs into a
// __device__ scratch struct; cudaMemcpyToSymbolAsync (D2D, capturable) loads
// the constant bank; main kernel is R4's 2-rows/thread f32x2 structure.

#define NTHREADS 256
typedef unsigned long long ull;

struct Params {
    ull   w2p[256];   // (16,16) packed {wd2, wo2}
    ull   w1p[32];    // (2,16)  packed {wd1, wo1}
    ull   b1p[16];    // {bd1, bo1}
    ull   b2p[16];    // {bd2, bo2}
    float wd3[32];    // (16,2)
    float wo3[16];    // (16,1)
    float bd3[2];
    float bo3[2];     // [1] is padding
};

__device__    Params g_pack;   // scratch filled by prep kernel
__constant__  Params c_p;      // uniform-port home of the weights

__device__ __forceinline__ ull pack2(float lo, float hi) {
    ull r; asm("mov.b64 %0, {%1, %2};" : "=l"(r) : "f"(lo), "f"(hi)); return r;
}
__device__ __forceinline__ void unpack2(ull v, float& lo, float& hi) {
    asm("mov.b64 {%0, %1}, %2;" : "=f"(lo), "=f"(hi) : "l"(v));
}
__device__ __forceinline__ ull fma2(ull a, ull b, ull c) {
    ull d; asm("fma.rn.f32x2 %0, %1, %2, %3;" : "=l"(d) : "l"(a), "l"(b), "l"(c)); return d;
}
__device__ __forceinline__ float tanh_ap(float x) {
    float y; asm("tanh.approx.f32 %0, %1;" : "=f"(y) : "f"(x)); return y;
}
__device__ __forceinline__ ull tanh2(ull v) {
    float lo, hi; unpack2(v, lo, hi);
    return pack2(tanh_ap(lo), tanh_ap(hi));
}

__global__ void pack_kernel(
    const float* __restrict__ w_d1, const float* __restrict__ w_d2,
    const float* __restrict__ w_d3, const float* __restrict__ w_o1,
    const float* __restrict__ w_o2, const float* __restrict__ w_o3,
    const float* __restrict__ b_d1, const float* __restrict__ b_d2,
    const float* __restrict__ b_d3, const float* __restrict__ b_o1,
    const float* __restrict__ b_o2, const float* __restrict__ b_o3)
{
    const int t = threadIdx.x;
    if (t < 256) g_pack.w2p[t] = pack2(w_d2[t], w_o2[t]);
    if (t < 32)  { g_pack.w1p[t] = pack2(w_d1[t], w_o1[t]); g_pack.wd3[t] = w_d3[t]; }
    if (t < 16)  { g_pack.b1p[t] = pack2(b_d1[t], b_o1[t]);
                   g_pack.b2p[t] = pack2(b_d2[t], b_o2[t]);
                   g_pack.wo3[t] = w_o3[t]; }
    if (t < 2)   g_pack.bd3[t] = b_d3[t];
    if (t == 0)  { g_pack.bo3[0] = b_o3[0]; g_pack.bo3[1] = 0.0f; }
}

struct U2 { ull x, y; };

__global__ __launch_bounds__(NTHREADS, 2) void damping_kernel(
    const float4* __restrict__ x, float4* __restrict__ out, int npairs)
{
    const int p = blockIdx.x * NTHREADS + threadIdx.x;
    if (p >= npairs) return;

    // Two adjacent rows per thread: A = 2p, B = 2p+1 -> one float4.
    const float4 xi = x[p];
    const ull x0A = pack2(xi.x, xi.x), x1A = pack2(xi.y, xi.y);
    const ull x0B = pack2(xi.z, xi.z), x1B = pack2(xi.w, xi.w);

    // ---------------- fused layer-1 + layer-2 ----------------
    ull accA[16], accB[16];
    #pragma unroll
    for (int j = 0; j < 16; j++) { accA[j] = c_p.b2p[j]; accB[j] = accA[j]; }

    #pragma unroll
    for (int k = 0; k < 16; k++) {
        const ull w1k0 = c_p.w1p[k];
        const ull w1k1 = c_p.w1p[16 + k];
        const ull b1k  = c_p.b1p[k];
        const ull hA = tanh2(fma2(x0A, w1k0, fma2(x1A, w1k1, b1k)));
        const ull hB = tanh2(fma2(x0B, w1k0, fma2(x1B, w1k1, b1k)));

        #pragma unroll
        for (int j2 = 0; j2 < 8; j2++) {
            const ull w0 = c_p.w2p[k * 16 + j2 * 2 + 0];
            const ull w1 = c_p.w2p[k * 16 + j2 * 2 + 1];
            accA[j2 * 2 + 0] = fma2(hA, w0, accA[j2 * 2 + 0]);
            accA[j2 * 2 + 1] = fma2(hA, w1, accA[j2 * 2 + 1]);
            accB[j2 * 2 + 0] = fma2(hB, w0, accB[j2 * 2 + 0]);
            accB[j2 * 2 + 1] = fma2(hB, w1, accB[j2 * 2 + 1]);
        }
    }

    // ---------------- layer 3 (scalar, nets diverge) ----------------
    float d30A = c_p.bd3[0], d31A = c_p.bd3[1], cA = c_p.bo3[0];
    float d30B = d30A,       d31B = d31A,       cB = cA;
    #pragma unroll
    for (int k = 0; k < 16; k++) {
        const float w3a = c_p.wd3[k * 2 + 0];
        const float w3b = c_p.wd3[k * 2 + 1];
        const float w3c = c_p.wo3[k];
        float pdA, poA; unpack2(accA[k], pdA, poA);
        float pdB, poB; unpack2(accB[k], pdB, poB);
        const float gdA = tanh_ap(pdA), goA = tanh_ap(poA);
        const float gdB = tanh_ap(pdB), goB = tanh_ap(poB);
        d30A = fmaf(gdA, w3a, d30A);  d30B = fmaf(gdB, w3a, d30B);
        d31A = fmaf(gdA, w3b, d31A);  d31B = fmaf(gdB, w3b, d31B);
        cA   = fmaf(goA, w3c, cA);    cB   = fmaf(goB, w3c, cB);
    }

    // ---------------- damping-matrix epilogue ----------------
    const float aA = (fmaxf(d30A, 0.0f) + 0.001f) * xi.x;
    const float bA = (fmaxf(d31A, 0.0f) + 0.001f) * xi.y;
    const float aB = (fmaxf(d30B, 0.0f) + 0.001f) * xi.z;
    const float bB = (fmaxf(d31B, 0.0f) + 0.001f) * xi.w;

    const float acA = aA * cA;
    const float acB = aB * cB;
    float4 o;
    o.x = fmaf(aA * aA, xi.x, acA * xi.y);
    o.y = fmaf(acA, xi.x, fmaf(cA, cA, bA * bA) * xi.y);
    o.z = fmaf(aB * aB, xi.z, acB * xi.w);
    o.w = fmaf(acB, xi.z, fmaf(cB, cB, bB * bB) * xi.w);
    out[p] = o;
}

extern "C" void kernel_launch(void* const* d_in, const int* in_sizes, int n_in,
                              void* d_out, int out_size) {
    const float4* x   = (const float4*)d_in[0];
    const float* w_d1 = (const float*)d_in[1];
    const float* w_d2 = (const float*)d_in[2];
    const float* w_d3 = (const float*)d_in[3];
    const float* w_o1 = (const float*)d_in[4];
    const float* w_o2 = (const float*)d_in[5];
    const float* w_o3 = (const float*)d_in[6];
    const float* b_d1 = (const float*)d_in[7];
    const float* b_d2 = (const float*)d_in[8];
    const float* b_d3 = (const float*)d_in[9];
    const float* b_o1 = (const float*)d_in[10];
    const float* b_o2 = (const float*)d_in[11];
    const float* b_o3 = (const float*)d_in[12];
    float4* out = (float4*)d_out;

    // 1) pack weights into __device__ scratch
    pack_kernel<<<1, 256>>>(w_d1, w_d2, w_d3, w_o1, w_o2, w_o3,
                            b_d1, b_d2, b_d3, b_o1, b_o2, b_o3);

    // 2) D2D copy scratch -> constant bank (graph-capturable memcpy node)
    void* src = nullptr;
    cudaGetSymbolAddress(&src, g_pack);
    cudaMemcpyToSymbolAsync(c_p, src, sizeof(Params), 0,
                            cudaMemcpyDeviceToDevice, 0);

    // 3) main kernel
    const int nrows  = in_sizes[0] / 2;
    const int npairs = nrows / 2;               // B = 4194304 is even
    const int grid   = (npairs + NTHREADS - 1) / NTHREADS;
    damping_kernel<<<grid, NTHREADS>>>(x, out, npairs);
}

// round 6
// speedup vs baseline: 2.3606x; 1.0723x over previous
#include <cuda_runtime.h>
#include <cuda_bf16.h>

// Damping_27066883900008 R6: R5 (constant-bank LDCU weights) + layer-3 and
// epilogue packed across the row pair {A,B} with f32x2; pre-duplicated {w,w}
// constant pairs; 16B-aligned w2 pairs for LDCU.128.

#define NTHREADS 256
typedef unsigned long long ull;

struct __align__(16) Params {
    ull   w2p[256];    // (16,16) packed {wd2, wo2}, 16B-aligned pairs
    ull   w1p[32];     // (2,16)  packed {wd1, wo1}
    ull   b1p[16];     // {bd1, bo1}
    ull   b2p[16];     // {bd2, bo2}
    ull   wd3ap[16];   // {wd3[k][0], wd3[k][0]}  (dup for {A,B} fma2)
    ull   wd3bp[16];   // {wd3[k][1], wd3[k][1]}
    ull   wo3p[16];    // {wo3[k],    wo3[k]}
    ull   bd30p;       // {bd3[0], bd3[0]}
    ull   bd31p;       // {bd3[1], bd3[1]}
    ull   bo3p;        // {bo3[0], bo3[0]}
};

__device__    Params g_pack;   // scratch filled by prep kernel
__constant__  Params c_p;      // uniform-port home of the weights

__device__ __forceinline__ ull pack2(float lo, float hi) {
    ull r; asm("mov.b64 %0, {%1, %2};" : "=l"(r) : "f"(lo), "f"(hi)); return r;
}
__device__ __forceinline__ void unpack2(ull v, float& lo, float& hi) {
    asm("mov.b64 {%0, %1}, %2;" : "=f"(lo), "=f"(hi) : "l"(v));
}
__device__ __forceinline__ ull fma2(ull a, ull b, ull c) {
    ull d; asm("fma.rn.f32x2 %0, %1, %2, %3;" : "=l"(d) : "l"(a), "l"(b), "l"(c)); return d;
}
__device__ __forceinline__ ull mul2(ull a, ull b) {
    ull d; asm("mul.rn.f32x2 %0, %1, %2;" : "=l"(d) : "l"(a), "l"(b)); return d;
}
__device__ __forceinline__ ull add2(ull a, ull b) {
    ull d; asm("add.rn.f32x2 %0, %1, %2;" : "=l"(d) : "l"(a), "l"(b)); return d;
}
__device__ __forceinline__ float tanh_ap(float x) {
    float y; asm("tanh.approx.f32 %0, %1;" : "=f"(y) : "f"(x)); return y;
}
__device__ __forceinline__ ull tanh2(ull v) {
    float lo, hi; unpack2(v, lo, hi);
    return pack2(tanh_ap(lo), tanh_ap(hi));
}

__global__ void pack_kernel(
    const float* __restrict__ w_d1, const float* __restrict__ w_d2,
    const float* __restrict__ w_d3, const float* __restrict__ w_o1,
    const float* __restrict__ w_o2, const float* __restrict__ w_o3,
    const float* __restrict__ b_d1, const float* __restrict__ b_d2,
    const float* __restrict__ b_d3, const float* __restrict__ b_o1,
    const float* __restrict__ b_o2, const float* __restrict__ b_o3)
{
    const int t = threadIdx.x;
    if (t < 256) g_pack.w2p[t] = pack2(w_d2[t], w_o2[t]);
    if (t < 32)  g_pack.w1p[t] = pack2(w_d1[t], w_o1[t]);
    if (t < 16)  {
        g_pack.b1p[t]   = pack2(b_d1[t], b_o1[t]);
        g_pack.b2p[t]   = pack2(b_d2[t], b_o2[t]);
        g_pack.wd3ap[t] = pack2(w_d3[t * 2 + 0], w_d3[t * 2 + 0]);
        g_pack.wd3bp[t] = pack2(w_d3[t * 2 + 1], w_d3[t * 2 + 1]);
        g_pack.wo3p[t]  = pack2(w_o3[t], w_o3[t]);
    }
    if (t == 0) {
        g_pack.bd30p = pack2(b_d3[0], b_d3[0]);
        g_pack.bd31p = pack2(b_d3[1], b_d3[1]);
        g_pack.bo3p  = pack2(b_o3[0], b_o3[0]);
    }
}

__global__ __launch_bounds__(NTHREADS, 2) void damping_kernel(
    const float4* __restrict__ x, float4* __restrict__ out, int npairs)
{
    const int p = blockIdx.x * NTHREADS + threadIdx.x;
    if (p >= npairs) return;

    // Two adjacent rows per thread: A = 2p, B = 2p+1 -> one float4.
    const float4 xi = x[p];
    const ull x0A = pack2(xi.x, xi.x), x1A = pack2(xi.y, xi.y);
    const ull x0B = pack2(xi.z, xi.z), x1B = pack2(xi.w, xi.w);

    // ---------------- fused layer-1 + layer-2 (packed {d,o}) ----------------
    ull accA[16], accB[16];
    #pragma unroll
    for (int j = 0; j < 16; j++) { accA[j] = c_p.b2p[j]; accB[j] = accA[j]; }

    #pragma unroll
    for (int k = 0; k < 16; k++) {
        const ull w1k0 = c_p.w1p[k];
        const ull w1k1 = c_p.w1p[16 + k];
        const ull b1k  = c_p.b1p[k];
        const ull hA = tanh2(fma2(x0A, w1k0, fma2(x1A, w1k1, b1k)));
        const ull hB = tanh2(fma2(x0B, w1k0, fma2(x1B, w1k1, b1k)));

        #pragma unroll
        for (int j2 = 0; j2 < 8; j2++) {
            // 16B-aligned pair -> LDCU.128 eligible
            const ulonglong2 w =
                *reinterpret_cast<const ulonglong2*>(&c_p.w2p[k * 16 + j2 * 2]);
            accA[j2 * 2 + 0] = fma2(hA, w.x, accA[j2 * 2 + 0]);
            accA[j2 * 2 + 1] = fma2(hA, w.y, accA[j2 * 2 + 1]);
            accB[j2 * 2 + 0] = fma2(hB, w.x, accB[j2 * 2 + 0]);
            accB[j2 * 2 + 1] = fma2(hB, w.y, accB[j2 * 2 + 1]);
        }
    }

    // ---------------- layer 3 (packed {A,B}) ----------------
    ull d30p = c_p.bd30p, d31p = c_p.bd31p, cp = c_p.bo3p;
    #pragma unroll
    for (int k = 0; k < 16; k++) {
        float pdA, poA; unpack2(accA[k], pdA, poA);
        float pdB, poB; unpack2(accB[k], pdB, poB);
        const ull gdp = pack2(tanh_ap(pdA), tanh_ap(pdB));
        const ull gop = pack2(tanh_ap(poA), tanh_ap(poB));
        d30p = fma2(gdp, c_p.wd3ap[k], d30p);
        d31p = fma2(gdp, c_p.wd3bp[k], d31p);
        cp   = fma2(gop, c_p.wo3p[k],  cp);
    }

    // ---------------- damping-matrix epilogue (packed {A,B}) ----------------
    float d30A, d30B, d31A, d31B;
    unpack2(d30p, d30A, d30B);
    unpack2(d31p, d31A, d31B);

    const ull x0p = pack2(xi.x, xi.z);            // {x0_A, x0_B}
    const ull x1p = pack2(xi.y, xi.w);            // {x1_A, x1_B}
    const ull k001 = pack2(0.001f, 0.001f);

    // relu on alu pipe (FMNMX), then packed math
    const ull r0 = pack2(fmaxf(d30A, 0.0f), fmaxf(d30B, 0.0f));
    const ull r1 = pack2(fmaxf(d31A, 0.0f), fmaxf(d31B, 0.0f));
    const ull ap = mul2(add2(r0, k001), x0p);     // a = (relu(d30)+eps)*x0
    const ull bp = mul2(add2(r1, k001), x1p);     // b = (relu(d31)+eps)*x1

    const ull acp  = mul2(ap, cp);
    const ull aap  = mul2(ap, ap);
    const ull ccbb = fma2(cp, cp, mul2(bp, bp));
    const ull D0p  = fma2(aap, x0p, mul2(acp, x1p));
    const ull D1p  = fma2(acp, x0p, mul2(ccbb, x1p));

    float4 o;
    float D0A, D0B, D1A, D1B;
    unpack2(D0p, D0A, D0B);
    unpack2(D1p, D1A, D1B);
    o.x = D0A; o.y = D1A; o.z = D0B; o.w = D1B;
    out[p] = o;
}

extern "C" void kernel_launch(void* const* d_in, const int* in_sizes, int n_in,
                              void* d_out, int out_size) {
    const float4* x   = (const float4*)d_in[0];
    const float* w_d1 = (const float*)d_in[1];
    const float* w_d2 = (const float*)d_in[2];
    const float* w_d3 = (const float*)d_in[3];
    const float* w_o1 = (const float*)d_in[4];
    const float* w_o2 = (const float*)d_in[5];
    const float* w_o3 = (const float*)d_in[6];
    const float* b_d1 = (const float*)d_in[7];
    const float* b_d2 = (const float*)d_in[8];
    const float* b_d3 = (const float*)d_in[9];
    const float* b_o1 = (const float*)d_in[10];
    const float* b_o2 = (const float*)d_in[11];
    const float* b_o3 = (const float*)d_in[12];
    float4* out = (float4*)d_out;

    // 1) pack weights into __device__ scratch
    pack_kernel<<<1, 256>>>(w_d1, w_d2, w_d3, w_o1, w_o2, w_o3,
                            b_d1, b_d2, b_d3, b_o1, b_o2, b_o3);

    // 2) D2D copy scratch -> constant bank (graph-capturable memcpy node)
    void* src = nullptr;
    cudaGetSymbolAddress(&src, g_pack);
    cudaMemcpyToSymbolAsync(c_p, src, sizeof(Params), 0,
                            cudaMemcpyDeviceToDevice, 0);

    // 3) main kernel
    const int nrows  = in_sizes[0] / 2;
    const int npairs = nrows / 2;               // B = 4194304 is even
    const int grid   = (npairs + NTHREADS - 1) / NTHREADS;
    damping_kernel<<<grid, NTHREADS>>>(x, out, npairs);
}